// round 3
// baseline (speedup 1.0000x reference)
#include <cuda_runtime.h>
#include <math.h>
#include <stdint.h>

#define NN   50000
#define EE   800000
#define IND  128
#define HIDD 256
#define OUTD 40
#define TOT  (EE + NN)
#define BN_EPS 1e-5f

// ---------------- scratch (device globals: alloc-guard compliant) ----------------
__device__ __align__(16) float g_t1[(size_t)NN * HIDD];
__device__ __align__(16) float g_t2[(size_t)NN * HIDD];
__device__ float g_dinv[NN];
__device__ int   g_deg[NN];
__device__ int   g_cnt[NN];
__device__ int   g_off[NN + 1];
__device__ int   g_row[EE];
__device__ int   g_col[EE];
__device__ int   g_csr_col[TOT];
__device__ float g_csr_w[TOT];
__device__ float g_sum[HIDD];
__device__ float g_sumsq[HIDD];
__device__ float g_bn_s[HIDD];
__device__ float g_bn_t[HIDD];
__device__ int   g_is64;

static inline int cdiv(int a, int b) { return (a + b - 1) / b; }

// ---------------- tf32 helpers ----------------
__device__ __forceinline__ float to_tf32(float x) {
    uint32_t u;
    asm("cvt.rna.tf32.f32 %0, %1;" : "=r"(u) : "f"(x));
    return __uint_as_float(u);
}

__device__ __forceinline__ void mma_tf32(float c[4], const uint32_t a[4], const uint32_t b[2]) {
    asm volatile(
        "mma.sync.aligned.m16n8k8.row.col.f32.tf32.tf32.f32 "
        "{%0,%1,%2,%3}, {%4,%5,%6,%7}, {%8,%9}, {%0,%1,%2,%3};\n"
        : "+f"(c[0]), "+f"(c[1]), "+f"(c[2]), "+f"(c[3])
        : "r"(a[0]), "r"(a[1]), "r"(a[2]), "r"(a[3]), "r"(b[0]), "r"(b[1]));
}

// ---------------- preprocessing ----------------
__global__ void k_detect_init(const void* ei) {
    int i = blockIdx.x * blockDim.x + threadIdx.x;
    if (i < NN) { g_deg[i] = 1; g_cnt[i] = 1; }   // self-loop
    if (i == 0) {
        const unsigned long long* p = (const unsigned long long*)ei;
        int is64 = 1;
        for (int q = 0; q < 8; q++) if (p[q] >= (unsigned long long)NN) is64 = 0;
        g_is64 = is64;
    }
}

__global__ void k_convert_deg(const void* ei) {
    int e = blockIdx.x * blockDim.x + threadIdx.x;
    if (e >= EE) return;
    int r, c;
    if (g_is64) {
        const long long* p = (const long long*)ei;
        r = (int)p[e];
        c = (int)p[EE + e];
    } else {
        const int* p = (const int*)ei;
        r = p[e];
        c = p[EE + e];
    }
    g_row[e] = r;
    g_col[e] = c;
    atomicAdd(&g_deg[c], 1);
    atomicAdd(&g_cnt[r], 1);
}

// scan of g_cnt -> g_off, plus dinv, then reset g_cnt
__global__ void k_scan_dinv() {
    __shared__ int part[1024];
    int t = threadIdx.x;
    const int CH = (NN + 1023) / 1024;
    int b = t * CH;
    int e = min(NN, b + CH);
    int s = 0;
    for (int i = b; i < e; i++) {
        s += g_cnt[i];
        g_dinv[i] = rsqrtf((float)g_deg[i]);
    }
    part[t] = s;
    __syncthreads();
    for (int off = 1; off < 1024; off <<= 1) {
        int v = (t >= off) ? part[t - off] : 0;
        __syncthreads();
        part[t] += v;
        __syncthreads();
    }
    int pre = (t == 0) ? 0 : part[t - 1];
    for (int i = b; i < e; i++) {
        g_off[i] = pre;
        pre += g_cnt[i];
    }
    if (t == 1023) g_off[NN] = part[1023];
    __syncthreads();
    for (int i = b; i < e; i++) g_cnt[i] = 0;
}

// fill CSR; also zero BN stat accumulators (consumed by gemm1 STATS epilogue)
__global__ void k_fill() {
    int idx = blockIdx.x * blockDim.x + threadIdx.x;
    if (idx < HIDD) { g_sum[idx] = 0.f; g_sumsq[idx] = 0.f; }
    if (idx >= TOT) return;
    int r, c; float w;
    if (idx < EE) {
        r = g_row[idx];
        c = g_col[idx];
        w = g_dinv[r] * g_dinv[c];
    } else {
        r = idx - EE;
        c = r;
        float d = g_dinv[r];
        w = d * d;
    }
    int pos = g_off[r] + atomicAdd(&g_cnt[r], 1);
    g_csr_col[pos] = c;
    g_csr_w[pos]   = w;
}

// ---------------- big tensor-core GEMM: 512 thr, BM=128 BN=128 BK=32 ----------------
// FUSE:  a' = relu(a*g_bn_s[k]+g_bn_t[k]) folded into A smem store
// STATS: per-column sum/sumsq of final C accumulated into g_sum/g_sumsq
// ZERO:  block(0,0) zeroes g_sum/g_sumsq (for the *next* stats pass)
template <bool FUSE, bool BIAS, bool STATS, bool ZERO>
__global__ void __launch_bounds__(512) k_gemm_tc2(
    const float* __restrict__ A, const float* __restrict__ B,
    const float* __restrict__ bias, float* __restrict__ C,
    int M, int K, int Ncols)
{
    constexpr int BM = 128, BN = 128, BK = 32;
    constexpr int ASTR = 36, BSTR = 136;
    __shared__ float As[BM * ASTR];
    __shared__ float Bs[BK * BSTR];

    const int tid  = threadIdx.x;
    const int warp = tid >> 5, lane = tid & 31;
    const int gid  = lane >> 2, tg = lane & 3;
    const int wm   = (warp & 3) * 32;    // 4 warps along M
    const int wn   = (warp >> 2) * 32;   // 4 warps along N
    const int bm   = blockIdx.y * BM, bn = blockIdx.x * BN;

    if (ZERO && blockIdx.x == 0 && blockIdx.y == 0 && tid < HIDD) {
        g_sum[tid] = 0.f; g_sumsq[tid] = 0.f;
    }

    float c[2][4][4];
#pragma unroll
    for (int i = 0; i < 2; i++)
#pragma unroll
        for (int j = 0; j < 4; j++)
#pragma unroll
            for (int q = 0; q < 4; q++) c[i][j][q] = 0.f;

    float4 areg[2], breg[2];

    // prologue
#pragma unroll
    for (int r = 0; r < 2; r++) {
        int idx = tid + r * 512;
        int m = idx >> 3, c4 = idx & 7;
        int gm = bm + m;
        areg[r] = make_float4(0.f, 0.f, 0.f, 0.f);
        if (gm < M) areg[r] = *reinterpret_cast<const float4*>(A + (size_t)gm * K + c4 * 4);
    }
#pragma unroll
    for (int r = 0; r < 2; r++) {
        int idx = tid + r * 512;
        int kk = idx >> 5, n4 = idx & 31;
        breg[r] = *reinterpret_cast<const float4*>(B + (size_t)kk * Ncols + bn + n4 * 4);
    }

    for (int k0 = 0; k0 < K; k0 += BK) {
        // store staged regs to smem (FUSE + tf32)
#pragma unroll
        for (int r = 0; r < 2; r++) {
            int idx = tid + r * 512;
            int m = idx >> 3, c4 = idx & 7;
            float4 v = areg[r];
            if (FUSE) {
                int gk = k0 + c4 * 4;
                v.x = fmaxf(0.f, fmaf(v.x, g_bn_s[gk + 0], g_bn_t[gk + 0]));
                v.y = fmaxf(0.f, fmaf(v.y, g_bn_s[gk + 1], g_bn_t[gk + 1]));
                v.z = fmaxf(0.f, fmaf(v.z, g_bn_s[gk + 2], g_bn_t[gk + 2]));
                v.w = fmaxf(0.f, fmaf(v.w, g_bn_s[gk + 3], g_bn_t[gk + 3]));
            }
            *reinterpret_cast<float4*>(&As[m * ASTR + c4 * 4]) =
                make_float4(to_tf32(v.x), to_tf32(v.y), to_tf32(v.z), to_tf32(v.w));
        }
#pragma unroll
        for (int r = 0; r < 2; r++) {
            int idx = tid + r * 512;
            int kk = idx >> 5, n4 = idx & 31;
            float4 v = breg[r];
            *reinterpret_cast<float4*>(&Bs[kk * BSTR + n4 * 4]) =
                make_float4(to_tf32(v.x), to_tf32(v.y), to_tf32(v.z), to_tf32(v.w));
        }
        __syncthreads();

        // prefetch next tile
        if (k0 + BK < K) {
            int kn = k0 + BK;
#pragma unroll
            for (int r = 0; r < 2; r++) {
                int idx = tid + r * 512;
                int m = idx >> 3, c4 = idx & 7;
                int gm = bm + m;
                areg[r] = make_float4(0.f, 0.f, 0.f, 0.f);
                if (gm < M) areg[r] = *reinterpret_cast<const float4*>(A + (size_t)gm * K + kn + c4 * 4);
            }
#pragma unroll
            for (int r = 0; r < 2; r++) {
                int idx = tid + r * 512;
                int kk = idx >> 5, n4 = idx & 31;
                breg[r] = *reinterpret_cast<const float4*>(B + (size_t)(kn + kk) * Ncols + bn + n4 * 4);
            }
        }

        // compute
#pragma unroll
        for (int kc = 0; kc < 4; kc++) {
            int kb = kc * 8 + tg;
            uint32_t a[2][4], b[4][2];
#pragma unroll
            for (int am = 0; am < 2; am++) {
                int mr = wm + am * 16 + gid;
                a[am][0] = __float_as_uint(As[mr * ASTR + kb]);
                a[am][1] = __float_as_uint(As[(mr + 8) * ASTR + kb]);
                a[am][2] = __float_as_uint(As[mr * ASTR + kb + 4]);
                a[am][3] = __float_as_uint(As[(mr + 8) * ASTR + kb + 4]);
            }
#pragma unroll
            for (int bi = 0; bi < 4; bi++) {
                int nc = wn + bi * 8 + gid;
                b[bi][0] = __float_as_uint(Bs[kb * BSTR + nc]);
                b[bi][1] = __float_as_uint(Bs[(kb + 4) * BSTR + nc]);
            }
#pragma unroll
            for (int am = 0; am < 2; am++)
#pragma unroll
                for (int bi = 0; bi < 4; bi++)
                    mma_tf32(c[am][bi], a[am], b[bi]);
        }
        __syncthreads();
    }

    // epilogue (+ optional fused BN stats)
    float csum[4][2], csq[4][2];
    if (STATS) {
#pragma unroll
        for (int bi = 0; bi < 4; bi++) {
            csum[bi][0] = csum[bi][1] = 0.f;
            csq[bi][0] = csq[bi][1] = 0.f;
        }
    }
#pragma unroll
    for (int am = 0; am < 2; am++) {
#pragma unroll
        for (int bi = 0; bi < 4; bi++) {
            int row = bm + wm + am * 16 + gid;
            int col = bn + wn + bi * 8 + 2 * tg;
            float bv0 = BIAS ? bias[col] : 0.f;
            float bv1 = BIAS ? bias[col + 1] : 0.f;
            float v0 = c[am][bi][0] + bv0, v1 = c[am][bi][1] + bv1;
            float v2 = c[am][bi][2] + bv0, v3 = c[am][bi][3] + bv1;
            if (row < M) {
                C[(size_t)row * Ncols + col]     = v0;
                C[(size_t)row * Ncols + col + 1] = v1;
                if (STATS) {
                    csum[bi][0] += v0; csq[bi][0] = fmaf(v0, v0, csq[bi][0]);
                    csum[bi][1] += v1; csq[bi][1] = fmaf(v1, v1, csq[bi][1]);
                }
            }
            if (row + 8 < M) {
                C[(size_t)(row + 8) * Ncols + col]     = v2;
                C[(size_t)(row + 8) * Ncols + col + 1] = v3;
                if (STATS) {
                    csum[bi][0] += v2; csq[bi][0] = fmaf(v2, v2, csq[bi][0]);
                    csum[bi][1] += v3; csq[bi][1] = fmaf(v3, v3, csq[bi][1]);
                }
            }
        }
    }
    if (STATS) {
#pragma unroll
        for (int bi = 0; bi < 4; bi++) {
#pragma unroll
            for (int j = 0; j < 2; j++) {
                float s = csum[bi][j], q = csq[bi][j];
#pragma unroll
                for (int m = 4; m < 32; m <<= 1) {
                    s += __shfl_xor_sync(0xFFFFFFFFu, s, m);
                    q += __shfl_xor_sync(0xFFFFFFFFu, q, m);
                }
                if (gid == 0) {
                    int col = bn + wn + bi * 8 + 2 * tg + j;
                    atomicAdd(&g_sum[col], s);
                    atomicAdd(&g_sumsq[col], q);
                }
            }
        }
    }
}

// ---------------- small GEMM (BN=64) for layer 3 ----------------
template <bool FUSE, bool BIAS>
__global__ void __launch_bounds__(256) k_gemm_tc(
    const float* __restrict__ A, const float* __restrict__ B,
    const float* __restrict__ bias, float* __restrict__ C,
    int M, int K, int Ncols)
{
    constexpr int BM = 128, BN = 64, BK = 32;
    constexpr int ASTR = 36, BSTR = 68;
    __shared__ float As[BM * ASTR];
    __shared__ float Bs[BK * BSTR];

    const int tid  = threadIdx.x;
    const int warp = tid >> 5, lane = tid & 31;
    const int gid  = lane >> 2, tg = lane & 3;
    const int wm   = (warp & 3) * 32;
    const int wn   = (warp >> 2) * 32;
    const int bm   = blockIdx.y * BM, bn = blockIdx.x * BN;

    float c[2][4][4];
#pragma unroll
    for (int i = 0; i < 2; i++)
#pragma unroll
        for (int j = 0; j < 4; j++)
#pragma unroll
            for (int q = 0; q < 4; q++) c[i][j][q] = 0.f;

    float4 areg[4];
    float  breg[8];

#pragma unroll
    for (int r = 0; r < 4; r++) {
        int idx = tid + r * 256;
        int m = idx >> 3, c4 = idx & 7;
        int gm = bm + m;
        areg[r] = make_float4(0.f, 0.f, 0.f, 0.f);
        if (gm < M) areg[r] = *reinterpret_cast<const float4*>(A + (size_t)gm * K + c4 * 4);
    }
#pragma unroll
    for (int r = 0; r < 8; r++) {
        int idx = tid + r * 256;
        int kk = idx >> 6, n = idx & 63;
        breg[r] = (bn + n < Ncols) ? B[(size_t)kk * Ncols + bn + n] : 0.f;
    }

    for (int k0 = 0; k0 < K; k0 += BK) {
#pragma unroll
        for (int r = 0; r < 4; r++) {
            int idx = tid + r * 256;
            int m = idx >> 3, c4 = idx & 7;
            float4 v = areg[r];
            if (FUSE) {
                int gk = k0 + c4 * 4;
                v.x = fmaxf(0.f, fmaf(v.x, g_bn_s[gk + 0], g_bn_t[gk + 0]));
                v.y = fmaxf(0.f, fmaf(v.y, g_bn_s[gk + 1], g_bn_t[gk + 1]));
                v.z = fmaxf(0.f, fmaf(v.z, g_bn_s[gk + 2], g_bn_t[gk + 2]));
                v.w = fmaxf(0.f, fmaf(v.w, g_bn_s[gk + 3], g_bn_t[gk + 3]));
            }
            *reinterpret_cast<float4*>(&As[m * ASTR + c4 * 4]) =
                make_float4(to_tf32(v.x), to_tf32(v.y), to_tf32(v.z), to_tf32(v.w));
        }
#pragma unroll
        for (int r = 0; r < 8; r++) {
            int idx = tid + r * 256;
            int kk = idx >> 6, n = idx & 63;
            Bs[kk * BSTR + n] = to_tf32(breg[r]);
        }
        __syncthreads();

        if (k0 + BK < K) {
            int kn = k0 + BK;
#pragma unroll
            for (int r = 0; r < 4; r++) {
                int idx = tid + r * 256;
                int m = idx >> 3, c4 = idx & 7;
                int gm = bm + m;
                areg[r] = make_float4(0.f, 0.f, 0.f, 0.f);
                if (gm < M) areg[r] = *reinterpret_cast<const float4*>(A + (size_t)gm * K + kn + c4 * 4);
            }
#pragma unroll
            for (int r = 0; r < 8; r++) {
                int idx = tid + r * 256;
                int kk = idx >> 6, n = idx & 63;
                breg[r] = (bn + n < Ncols) ? B[(size_t)(kn + kk) * Ncols + bn + n] : 0.f;
            }
        }

#pragma unroll
        for (int kc = 0; kc < 4; kc++) {
            int kb = kc * 8 + tg;
            uint32_t a[2][4], b[4][2];
#pragma unroll
            for (int am = 0; am < 2; am++) {
                int mr = wm + am * 16 + gid;
                a[am][0] = __float_as_uint(As[mr * ASTR + kb]);
                a[am][1] = __float_as_uint(As[(mr + 8) * ASTR + kb]);
                a[am][2] = __float_as_uint(As[mr * ASTR + kb + 4]);
                a[am][3] = __float_as_uint(As[(mr + 8) * ASTR + kb + 4]);
            }
#pragma unroll
            for (int bi = 0; bi < 4; bi++) {
                int nc = wn + bi * 8 + gid;
                b[bi][0] = __float_as_uint(Bs[kb * BSTR + nc]);
                b[bi][1] = __float_as_uint(Bs[(kb + 4) * BSTR + nc]);
            }
#pragma unroll
            for (int am = 0; am < 2; am++)
#pragma unroll
                for (int bi = 0; bi < 4; bi++)
                    mma_tf32(c[am][bi], a[am], b[bi]);
        }
        __syncthreads();
    }

#pragma unroll
    for (int am = 0; am < 2; am++) {
#pragma unroll
        for (int bi = 0; bi < 4; bi++) {
            int row = bm + wm + am * 16 + gid;
            int col = bn + wn + bi * 8 + 2 * tg;
            float bv0 = 0.f, bv1 = 0.f;
            if (BIAS) {
                if (col < Ncols)     bv0 = bias[col];
                if (col + 1 < Ncols) bv1 = bias[col + 1];
            }
            if (row < M) {
                if (col < Ncols)     C[(size_t)row * Ncols + col]     = c[am][bi][0] + bv0;
                if (col + 1 < Ncols) C[(size_t)row * Ncols + col + 1] = c[am][bi][1] + bv1;
            }
            if (row + 8 < M) {
                if (col < Ncols)     C[(size_t)(row + 8) * Ncols + col]     = c[am][bi][2] + bv0;
                if (col + 1 < Ncols) C[(size_t)(row + 8) * Ncols + col + 1] = c[am][bi][3] + bv1;
            }
        }
    }
}

// ---------------- aggregation (unroll 4) ----------------
template <int F4, bool BIAS>
__global__ void __launch_bounds__(F4) k_agg_v(
    const float* __restrict__ h, const float* __restrict__ bias,
    float* __restrict__ out)
{
    const int F = F4 * 4;
    int i = blockIdx.x;
    int t = threadIdx.x;
    float4 acc = make_float4(0.f, 0.f, 0.f, 0.f);
    int p = g_off[i], end = g_off[i + 1];
    for (; p + 3 < end; p += 4) {
        int   c0 = __ldg(&g_csr_col[p]);
        int   c1 = __ldg(&g_csr_col[p + 1]);
        int   c2 = __ldg(&g_csr_col[p + 2]);
        int   c3 = __ldg(&g_csr_col[p + 3]);
        float w0 = __ldg(&g_csr_w[p]);
        float w1 = __ldg(&g_csr_w[p + 1]);
        float w2 = __ldg(&g_csr_w[p + 2]);
        float w3 = __ldg(&g_csr_w[p + 3]);
        float4 v0 = *reinterpret_cast<const float4*>(h + (size_t)c0 * F + t * 4);
        float4 v1 = *reinterpret_cast<const float4*>(h + (size_t)c1 * F + t * 4);
        float4 v2 = *reinterpret_cast<const float4*>(h + (size_t)c2 * F + t * 4);
        float4 v3 = *reinterpret_cast<const float4*>(h + (size_t)c3 * F + t * 4);
        acc.x = fmaf(w0, v0.x, fmaf(w1, v1.x, fmaf(w2, v2.x, fmaf(w3, v3.x, acc.x))));
        acc.y = fmaf(w0, v0.y, fmaf(w1, v1.y, fmaf(w2, v2.y, fmaf(w3, v3.y, acc.y))));
        acc.z = fmaf(w0, v0.z, fmaf(w1, v1.z, fmaf(w2, v2.z, fmaf(w3, v3.z, acc.z))));
        acc.w = fmaf(w0, v0.w, fmaf(w1, v1.w, fmaf(w2, v2.w, fmaf(w3, v3.w, acc.w))));
    }
    for (; p < end; p++) {
        int   c0 = __ldg(&g_csr_col[p]);
        float w0 = __ldg(&g_csr_w[p]);
        float4 v0 = *reinterpret_cast<const float4*>(h + (size_t)c0 * F + t * 4);
        acc.x = fmaf(w0, v0.x, acc.x);
        acc.y = fmaf(w0, v0.y, acc.y);
        acc.z = fmaf(w0, v0.z, acc.z);
        acc.w = fmaf(w0, v0.w, acc.w);
    }
    if (BIAS) {
        float4 b = *reinterpret_cast<const float4*>(bias + t * 4);
        acc.x += b.x; acc.y += b.y; acc.z += b.z; acc.w += b.w;
    }
    *reinterpret_cast<float4*>(out + (size_t)i * F + t * 4) = acc;
}

__global__ void __launch_bounds__(64) k_agg40(
    const float* __restrict__ h, const float* __restrict__ bias,
    float* __restrict__ out)
{
    int i = blockIdx.x;
    int t = threadIdx.x;
    if (t >= OUTD) return;
    float acc = 0.f;
    int p = g_off[i], end = g_off[i + 1];
    for (; p + 3 < end; p += 4) {
        int   c0 = __ldg(&g_csr_col[p]);
        int   c1 = __ldg(&g_csr_col[p + 1]);
        int   c2 = __ldg(&g_csr_col[p + 2]);
        int   c3 = __ldg(&g_csr_col[p + 3]);
        float w0 = __ldg(&g_csr_w[p]);
        float w1 = __ldg(&g_csr_w[p + 1]);
        float w2 = __ldg(&g_csr_w[p + 2]);
        float w3 = __ldg(&g_csr_w[p + 3]);
        float v0 = h[(size_t)c0 * OUTD + t];
        float v1 = h[(size_t)c1 * OUTD + t];
        float v2 = h[(size_t)c2 * OUTD + t];
        float v3 = h[(size_t)c3 * OUTD + t];
        acc = fmaf(w0, v0, fmaf(w1, v1, fmaf(w2, v2, fmaf(w3, v3, acc))));
    }
    for (; p < end; p++) {
        int   c0 = __ldg(&g_csr_col[p]);
        float w0 = __ldg(&g_csr_w[p]);
        acc = fmaf(w0, h[(size_t)c0 * OUTD + t], acc);
    }
    out[(size_t)i * OUTD + t] = acc + bias[t];
}

// ---------------- batchnorm stats (layer 2 only; layer 1 fused in gemm1) ----------------
__global__ void __launch_bounds__(64) k_stats(const float* __restrict__ h) {
    int t = threadIdx.x;
    int rows_per_block = (NN + gridDim.x - 1) / gridDim.x;
    int r0 = blockIdx.x * rows_per_block;
    int r1 = min(NN, r0 + rows_per_block);
    float4 s = make_float4(0.f, 0.f, 0.f, 0.f);
    float4 q = make_float4(0.f, 0.f, 0.f, 0.f);
    for (int r = r0; r < r1; r++) {
        float4 v = *reinterpret_cast<const float4*>(h + (size_t)r * HIDD + t * 4);
        s.x += v.x; q.x = fmaf(v.x, v.x, q.x);
        s.y += v.y; q.y = fmaf(v.y, v.y, q.y);
        s.z += v.z; q.z = fmaf(v.z, v.z, q.z);
        s.w += v.w; q.w = fmaf(v.w, v.w, q.w);
    }
    atomicAdd(&g_sum[t * 4 + 0], s.x); atomicAdd(&g_sumsq[t * 4 + 0], q.x);
    atomicAdd(&g_sum[t * 4 + 1], s.y); atomicAdd(&g_sumsq[t * 4 + 1], q.y);
    atomicAdd(&g_sum[t * 4 + 2], s.z); atomicAdd(&g_sumsq[t * 4 + 2], q.z);
    atomicAdd(&g_sum[t * 4 + 3], s.w); atomicAdd(&g_sumsq[t * 4 + 3], q.w);
}

__global__ void k_bn_finalize(const float* __restrict__ gamma,
                              const float* __restrict__ beta) {
    int c = threadIdx.x;
    float mu = g_sum[c] * (1.f / NN);
    float var = g_sumsq[c] * (1.f / NN) - mu * mu;
    float rstd = rsqrtf(var + BN_EPS);
    float sc = rstd * gamma[c];
    g_bn_s[c] = sc;
    g_bn_t[c] = beta[c] - mu * sc;
}

// ---------------- log_softmax ----------------
__global__ void k_logsoftmax(const float* __restrict__ in, float* __restrict__ out) {
    int warp = (blockIdx.x * blockDim.x + threadIdx.x) >> 5;
    int lane = threadIdx.x & 31;
    if (warp >= NN) return;
    const float* r = in + (size_t)warp * OUTD;
    float v0 = (lane < OUTD) ? r[lane] : -INFINITY;
    float v1 = (lane + 32 < OUTD) ? r[lane + 32] : -INFINITY;
    float m = fmaxf(v0, v1);
#pragma unroll
    for (int off = 16; off > 0; off >>= 1)
        m = fmaxf(m, __shfl_xor_sync(0xFFFFFFFFu, m, off));
    float s = 0.f;
    if (lane < OUTD)      s += expf(v0 - m);
    if (lane + 32 < OUTD) s += expf(v1 - m);
#pragma unroll
    for (int off = 16; off > 0; off >>= 1)
        s += __shfl_xor_sync(0xFFFFFFFFu, s, off);
    float l = m + logf(s);
    if (lane < OUTD)      out[(size_t)warp * OUTD + lane] = v0 - l;
    if (lane + 32 < OUTD) out[(size_t)warp * OUTD + lane + 32] = v1 - l;
}

// ---------------- launch ----------------
extern "C" void kernel_launch(void* const* d_in, const int* in_sizes, int n_in,
                              void* d_out, int out_size) {
    const float* x     = (const float*)d_in[0];
    const void*  ei    = d_in[1];
    const float* W1    = (const float*)d_in[2];
    const float* b1    = (const float*)d_in[3];
    const float* W2    = (const float*)d_in[4];
    const float* b2    = (const float*)d_in[5];
    const float* W3    = (const float*)d_in[6];
    const float* b3    = (const float*)d_in[7];
    const float* gamma = (const float*)d_in[8];
    const float* beta  = (const float*)d_in[9];
    float* out = (float*)d_out;

    float *t1, *t2;
    cudaGetSymbolAddress((void**)&t1, g_t1);
    cudaGetSymbolAddress((void**)&t2, g_t2);

    // preprocessing (4 launches)
    k_detect_init<<<cdiv(NN, 256), 256>>>(ei);
    k_convert_deg<<<cdiv(EE, 256), 256>>>(ei);
    k_scan_dinv<<<1, 1024>>>();
    k_fill<<<cdiv(TOT, 256), 256>>>();

    dim3 gBig(2, cdiv(NN, 128));    // BN=128, Ncols=256
    dim3 g40(1, cdiv(NN, 128));     // BN=64,  Ncols=40

    // layer 1: agg-first, then GEMM with fused bias + BN stats
    k_agg_v<32, false><<<NN, 32>>>(x, nullptr, t1);
    k_gemm_tc2<false, true, true, false><<<gBig, 512>>>(t1, W1, b1, t2, NN, IND, HIDD);
    k_bn_finalize<<<1, HIDD>>>(gamma, beta);

    // layer 2: GEMM (BN+ReLU fused in, zeroes stats for next pass), agg, stats
    k_gemm_tc2<true, false, false, true><<<gBig, 512>>>(t2, W2, nullptr, t1, NN, HIDD, HIDD);
    k_agg_v<64, true><<<NN, 64>>>(t1, b2, t2);
    k_stats<<<512, 64>>>(t2);
    k_bn_finalize<<<1, HIDD>>>(gamma, beta);

    // layer 3
    k_gemm_tc<true, false><<<g40, 256>>>(t2, W3, nullptr, t1, NN, HIDD, OUTD);
    k_agg40<<<NN, 64>>>(t1, b3, t2);

    // log_softmax
    k_logsoftmax<<<cdiv(NN * 32, 256), 256>>>(t2, out);
}